// round 11
// baseline (speedup 1.0000x reference)
#include <cuda_runtime.h>

#define AN 360
#define PN 512
#define IMGN 512
#define IMGSQ (IMGN*IMGN)
#define ROW 20            // floats per window row (16 batches + 4 pad)
#define WMAX 28
#define TPB 128
#define NG (AN/2)         // 180 groups of 2 angles

#define FMA2(acc, g, w) asm("fma.rn.f32x2 %0,%1,%2,%0;" : "+l"(acc) : "l"(g), "l"(w))
#define PACK2(d, s)     asm("mov.b64 %0,{%1,%1};" : "=l"(d) : "f"(s))
// hat weight: exact lerp weight = sat(1 - |u|)
#define HAT(u) __saturatef(1.0f - fabsf(u))
// half-block barrier: 64 threads, ids 1/2
#define HALF_BAR(id) asm volatile("bar.sync %0, 64;" :: "r"(id) : "memory")

__global__ __launch_bounds__(TPB, 7)
void radon_bp(const float* __restrict__ sino,
              const float* __restrict__ thetas,
              const float* __restrict__ positions,
              float* __restrict__ out)
{
    __shared__ __align__(16) float4 s_acs[AN];                // {cos', sin', meta(bits), min(c,0)+min(s,0)}
    __shared__ __align__(16) float  s_win[3][2][WMAX * ROW];  // triple buffer x 2 angles

    const int tid = threadIdx.x;
    const int qid = tid & 63;       // quad id
    const int bh  = tid >> 6;       // batch half: 0 -> batches 0..7, 1 -> 8..15
    const int bar_id = 1 + bh;      // named barrier for this half
    // quad mapping: 8-lane phase = xq low 2 bits x yq low bit -> row spread < 8, conflict-free
    const int xq = (qid & 3) | (((qid >> 5) & 1) << 2);        // 0..7
    const int yq = ((qid >> 2) & 1) | (((qid >> 3) & 3) << 1); // 0..7
    const int x0 = blockIdx.x * 16;
    const int y0 = blockIdx.y * 16;

    const float pos0   = positions[0];
    const float inv_dp = 1.0f / (positions[1] - pos0);
    const float pb     = -pos0 * inv_dp;

    const float half = (IMGN - 1) * 0.5f;
    const float cxm = (float)x0 - half, cxM = cxm + 15.0f;
    const float cym = (float)y0 - half, cyM = cym + 15.0f;

    // ---- init: trig + window meta: ((lo+128) & 0xFFFF) | (W<<16); 0 = skip ----
    for (int a = tid; a < AN; a += TPB) {
        float th = thetas[a];
        float c = cosf(th) * inv_dp;
        float s = sinf(th) * inv_dp;
        float t0 = c * cxm, t1 = c * cxM;
        float u0 = s * cym, u1 = s * cyM;
        float tmin = fminf(t0, t1) + fminf(u0, u1) + pb;
        float tmax = fmaxf(t0, t1) + fmaxf(u0, u1) + pb;
        int lo = __float2int_rd(tmin) - 1;          // UNclamped
        int W  = (__float2int_rd(tmax) + 3) - lo + 1;
        W = min(W, WMAX);
        int meta = 0;
        if (lo < PN && lo + W > 0)
            meta = ((lo + 128) & 0xFFFF) | (W << 16);
        s_acs[a] = make_float4(c, s, __int_as_float(meta),
                               fminf(c, 0.0f) + fminf(s, 0.0f));
    }

    const float fx = (float)(x0 + 2 * xq) - half;
    const float fy = (float)(y0 + 2 * yq) - half;

    unsigned long long acc[4][4];   // [px][4 f32x2 = 8 batches (this half)]
    #pragma unroll
    for (int p = 0; p < 4; p++)
        #pragma unroll
        for (int q = 0; q < 4; q++) acc[p][q] = 0ull;

    // staging role: lane = window row, tid>>5 = batch quad (0..3)
    // producer/consumer graph is half-contained: bq 0,1 -> bh 0; bq 2,3 -> bh 1
    const int sr = tid & 31;
    const int bq = tid >> 5;
    const size_t BSTR = (size_t)AN * PN;
    const float* sino_q = sino + (size_t)(4 * bq) * BSTR;
    const int sofs = sr * ROW + 4 * bq;

    __syncthreads();   // s_acs visible (only full-block sync)

    // fetch one angle's window row (4 batches) into registers; true = do store
    auto fetch = [&](int a, int meta, float4& p) -> bool {
        if (!meta) return false;
        int lo = (meta & 0xFFFF) - 128;
        int W  = meta >> 16;
        if (sr >= W) return false;
        int rg  = lo + sr;
        bool inr = ((unsigned)rg < (unsigned)PN);
        int rc  = min(max(rg, 0), PN - 1);
        const float* b = sino_q + (size_t)a * PN + rc;
        p.x = __ldg(b);
        p.y = __ldg(b + BSTR);
        p.z = __ldg(b + 2 * BSTR);
        p.w = __ldg(b + 3 * BSTR);
        if (!inr) p = make_float4(0.f, 0.f, 0.f, 0.f);
        return true;
    };

    // ---- prologue: stage group 0 into buffer 0; prefetch group 1 ----
    {
        float4 p;
        #pragma unroll
        for (int ai = 0; ai < 2; ai++)
            if (fetch(ai, __float_as_int(s_acs[ai].z), p))
                *(float4*)&s_win[0][ai][sofs] = p;
    }
    float4 p0, p1;
    bool st0 = fetch(2, __float_as_int(s_acs[2].z), p0);
    bool st1 = fetch(3, __float_as_int(s_acs[3].z), p1);

    int buf_c = 0;

    #pragma unroll 1
    for (int g = 0; g < NG; g++) {
        const int a0 = 2 * g;
        const int buf_n = (buf_c == 2) ? 0 : buf_c + 1;

        // STS prefetched group g+1
        if (st0) *(float4*)&s_win[buf_n][0][sofs] = p0;
        if (st1) *(float4*)&s_win[buf_n][1][sofs] = p1;

        // LDG group g+2
        st0 = false; st1 = false;
        if (g + 2 < NG) {
            st0 = fetch(a0 + 4, __float_as_int(s_acs[a0 + 4].z), p0);
            st1 = fetch(a0 + 5, __float_as_int(s_acs[a0 + 5].z), p1);
        }

        HALF_BAR(bar_id);   // this half's win[buf_c] visible; halves fully decoupled

        #pragma unroll
        for (int ai = 0; ai < 2; ai++) {
            float4 acs = s_acs[a0 + ai];
            int m = __float_as_int(acs.z);
            if (!m) continue;
            const int lo = (m & 0xFFFF) - 128;
            const int W  = m >> 16;
            const float cp = acs.x, sp = acs.y;

            float f00 = fmaf(fx, cp, fmaf(fy, sp, pb));
            float fmn = f00 + acs.w;                   // + min(c,0)+min(s,0), precomputed
            int jb = min(max(__float2int_rd(fmn) - lo, 0), W - 4);

            float d0 = f00 - (float)(lo + jb);
            float d1 = d0 + cp;
            float d2 = d0 + sp;
            float d3 = d1 + sp;

            const float* win = &s_win[buf_c][ai][jb * ROW + 8 * bh];

            #pragma unroll
            for (int r = 0; r < 4; r++) {
                const ulonglong2* rp = (const ulonglong2*)(win + r * ROW);
                ulonglong2 ga = rp[0], gb = rp[1];   // 8 batches (this half)

                float fr = (float)r;
                float h0 = HAT(d0 - fr);
                float h1 = HAT(d1 - fr);
                float h2 = HAT(d2 - fr);
                float h3 = HAT(d3 - fr);
                unsigned long long W0, W1, W2, W3;
                PACK2(W0, h0); PACK2(W1, h1); PACK2(W2, h2); PACK2(W3, h3);

                FMA2(acc[0][0], ga.x, W0); FMA2(acc[0][1], ga.y, W0);
                FMA2(acc[0][2], gb.x, W0); FMA2(acc[0][3], gb.y, W0);

                FMA2(acc[1][0], ga.x, W1); FMA2(acc[1][1], ga.y, W1);
                FMA2(acc[1][2], gb.x, W1); FMA2(acc[1][3], gb.y, W1);

                FMA2(acc[2][0], ga.x, W2); FMA2(acc[2][1], ga.y, W2);
                FMA2(acc[2][2], gb.x, W2); FMA2(acc[2][3], gb.y, W2);

                FMA2(acc[3][0], ga.x, W3); FMA2(acc[3][1], ga.y, W3);
                FMA2(acc[3][2], gb.x, W3); FMA2(acc[3][3], gb.y, W3);
            }
        }

        buf_c = buf_n;
    }

    // ---- epilogue: out[b, 0, y, x]; this thread's 8 batches ----
    const int xb = x0 + 2 * xq;
    const int yb = y0 + 2 * yq;
    float* ob = out + (size_t)(8 * bh) * IMGSQ + (size_t)yb * IMGN + xb;
    #pragma unroll
    for (int q = 0; q < 4; q++) {
        float2 a0 = *(float2*)&acc[0][q];
        float2 a1 = *(float2*)&acc[1][q];
        float2 a2 = *(float2*)&acc[2][q];
        float2 a3 = *(float2*)&acc[3][q];
        size_t b0 = (size_t)(2 * q) * IMGSQ;
        size_t b1 = b0 + IMGSQ;
        *(float2*)(ob + b0)        = make_float2(a0.x, a1.x);
        *(float2*)(ob + b0 + IMGN) = make_float2(a2.x, a3.x);
        *(float2*)(ob + b1)        = make_float2(a0.y, a1.y);
        *(float2*)(ob + b1 + IMGN) = make_float2(a2.y, a3.y);
    }
}

extern "C" void kernel_launch(void* const* d_in, const int* in_sizes, int n_in,
                              void* d_out, int out_size)
{
    const float* sino      = (const float*)d_in[0];
    const float* thetas    = (const float*)d_in[1];
    const float* positions = (const float*)d_in[2];
    float* out             = (float*)d_out;

    dim3 grid(IMGN / 16, IMGN / 16);   // 32 x 32 = 1024 tiles
    radon_bp<<<grid, TPB>>>(sino, thetas, positions, out);
}

// round 12
// speedup vs baseline: 1.2728x; 1.2728x over previous
#include <cuda_runtime.h>

#define AN 360
#define PN 512
#define IMGN 512
#define IMGSQ (IMGN*IMGN)
#define ROW 20            // floats per window row (16 batches + 4 pad)
#define WMAX 32
#define TPB 128
#define NG (AN/2)         // 180 groups of 2 angles

#define FMA2(acc, g, w) asm("fma.rn.f32x2 %0,%1,%2,%0;" : "+l"(acc) : "l"(g), "l"(w))
#define PACK2(d, s)     asm("mov.b64 %0,{%1,%1};" : "=l"(d) : "f"(s))
// exact lerp hat weight: 1-|u| <= 1 always, so saturate == max(,0)
#define HAT(u) __saturatef(1.0f - fabsf(u))

__global__ __launch_bounds__(TPB, 7)
void radon_bp(const float* __restrict__ sino,
              const float* __restrict__ thetas,
              const float* __restrict__ positions,
              float* __restrict__ out)
{
    __shared__ __align__(16) float4 s_acs[AN];               // {cos', sin', meta(bits), min(c',0)}
    __shared__ __align__(16) float  s_win[3][2][WMAX * ROW]; // triple buffer x 2 angles

    const int tid = threadIdx.x;
    const int tx = tid >> 4;        // 0..7  x-pair
    const int yy = tid & 15;        // 0..15 y
    const int x0 = blockIdx.x * 16;
    const int y0 = blockIdx.y * 16;

    const float pos0   = positions[0];
    const float inv_dp = 1.0f / (positions[1] - pos0);
    const float pb     = -pos0 * inv_dp;

    const float half = (IMGN - 1) * 0.5f;
    const float cxm = (float)x0 - half, cxM = cxm + 15.0f;
    const float cym = (float)y0 - half, cyM = cym + 15.0f;

    // ---- init: trig + window meta (lo | (W-3)<<9) ----
    for (int a = tid; a < AN; a += TPB) {
        float th = thetas[a];
        float c = cosf(th) * inv_dp;
        float s = sinf(th) * inv_dp;
        float t0 = c * cxm, t1 = c * cxM;
        float u0 = s * cym, u1 = s * cyM;
        float tmin = fminf(t0, t1) + fminf(u0, u1) + pb;
        float tmax = fmaxf(t0, t1) + fmaxf(u0, u1) + pb;
        int ilo = __float2int_rd(tmin) - 1;
        int ihi = __float2int_rd(tmax) + 2;
        int meta = -1;
        if (ihi >= 0 && ilo <= PN - 1) {
            ilo = max(0, min(PN - 1, ilo));
            ihi = max(0, min(PN - 1, ihi));
            if (ihi - ilo < 2) { ilo = max(0, min(ilo, PN - 3)); ihi = ilo + 2; }  // W >= 3
            meta = ilo | ((ihi - ilo - 2) << 9);   // lo | (W-3)<<9
        }
        s_acs[a] = make_float4(c, s, __int_as_float(meta), fminf(c, 0.0f));
    }

    const float fx = (float)(x0 + 2 * tx) - half;
    const float fy = (float)(y0 + yy) - half;

    unsigned long long accA[8], accB[8];
    #pragma unroll
    for (int m = 0; m < 8; m++) { accA[m] = 0ull; accB[m] = 0ull; }

    // staging role: lane = window row (coalesced LDG), warp = batch quad
    const int sr  = tid & 31;       // window row
    const int sbq = tid >> 5;       // batch quad 0..3
    const size_t BSTR = (size_t)AN * PN;
    const float* sino_q = sino + (size_t)(4 * sbq) * BSTR;
    const int sofs = sr * ROW + 4 * sbq;

    __syncthreads();   // s_acs visible

    // ---- prologue ----
    // stage group 0 directly into buffer 0
    #pragma unroll
    for (int ai = 0; ai < 2; ai++) {
        int m = __float_as_int(s_acs[ai].z);
        if (m >= 0 && sr < ((m >> 9) + 3)) {
            const float* s0 = sino_q + (size_t)ai * PN + (m & 511) + sr;
            float4 v;
            v.x = s0[0]; v.y = s0[BSTR]; v.z = s0[2*BSTR]; v.w = s0[3*BSTR];
            *(float4*)&s_win[0][ai][sofs] = v;
        }
    }
    // prefetch group 1 (angles 2,3) into registers
    float4 v0, v1;
    bool st0 = false, st1 = false;
    {
        int m0n = __float_as_int(s_acs[2].z);
        int m1n = __float_as_int(s_acs[3].z);
        if (m0n >= 0 && sr < ((m0n >> 9) + 3)) {
            const float* s0 = sino_q + (size_t)2 * PN + (m0n & 511) + sr;
            v0.x = __ldg(s0); v0.y = __ldg(s0 + BSTR);
            v0.z = __ldg(s0 + 2*BSTR); v0.w = __ldg(s0 + 3*BSTR);
            st0 = true;
        }
        if (m1n >= 0 && sr < ((m1n >> 9) + 3)) {
            const float* s0 = sino_q + (size_t)3 * PN + (m1n & 511) + sr;
            v1.x = __ldg(s0); v1.y = __ldg(s0 + BSTR);
            v1.z = __ldg(s0 + 2*BSTR); v1.w = __ldg(s0 + 3*BSTR);
            st1 = true;
        }
    }

    int buf_c = 0;

    #pragma unroll 1
    for (int g = 0; g < NG; g++) {
        const int a0 = 2 * g;
        const int buf_n = (buf_c == 2) ? 0 : buf_c + 1;

        // hoist this group's per-angle constants (loop-invariant smem) above barrier
        float4 acs0 = s_acs[a0];
        float4 acs1 = s_acs[a0 + 1];

        // STS the registers prefetched last iteration (window for group g+1)
        if (st0) *(float4*)&s_win[buf_n][0][sofs] = v0;
        if (st1) *(float4*)&s_win[buf_n][1][sofs] = v1;

        // LDG window for group g+2 (consumed by STS at top of next iteration)
        st0 = false; st1 = false;
        if (g + 2 < NG) {
            int m0n = __float_as_int(s_acs[a0 + 4].z);
            int m1n = __float_as_int(s_acs[a0 + 5].z);
            if (m0n >= 0 && sr < ((m0n >> 9) + 3)) {
                const float* s0 = sino_q + (size_t)(a0 + 4) * PN + (m0n & 511) + sr;
                v0.x = __ldg(s0); v0.y = __ldg(s0 + BSTR);
                v0.z = __ldg(s0 + 2*BSTR); v0.w = __ldg(s0 + 3*BSTR);
                st0 = true;
            }
            if (m1n >= 0 && sr < ((m1n >> 9) + 3)) {
                const float* s0 = sino_q + (size_t)(a0 + 5) * PN + (m1n & 511) + sr;
                v1.x = __ldg(s0); v1.y = __ldg(s0 + BSTR);
                v1.z = __ldg(s0 + 2*BSTR); v1.w = __ldg(s0 + 3*BSTR);
                st1 = true;
            }
        }

        __syncthreads();   // win[buf_c] (staged at iter g-1 top) visible

        #pragma unroll
        for (int ai = 0; ai < 2; ai++) {
            float4 acs = (ai == 0) ? acs0 : acs1;
            int m = __float_as_int(acs.z);
            if (m < 0) continue;
            const int lo = m & 511;
            const int W3 = m >> 9;     // W - 3

            float fA = fmaf(fx, acs.x, fmaf(fy, acs.y, pb));
            float fB = fA + acs.x;
            int im = __float2int_rd(fA + acs.w);   // fA + min(c',0) == min(fA,fB)
            int jb = min(max(im - lo, 0), W3);
            const ulonglong2* r0 = (const ulonglong2*)(&s_win[buf_c][ai][jb * ROW]);
            float jEf = (float)(lo + jb);

            float dA = fA - jEf, dB = fB - jEf;
            float w0A = HAT(dA);
            float w1A = HAT(dA - 1.0f);
            float w2A = HAT(dA - 2.0f);
            float w0B = HAT(dB);
            float w1B = HAT(dB - 1.0f);
            float w2B = HAT(dB - 2.0f);

            unsigned long long WA0, WA1, WA2, WB0, WB1, WB2;
            PACK2(WA0, w0A); PACK2(WA1, w1A); PACK2(WA2, w2A);
            PACK2(WB0, w0B); PACK2(WB1, w1B); PACK2(WB2, w2B);

            #pragma unroll
            for (int k = 0; k < 4; k++) {
                ulonglong2 g0 = r0[k];
                ulonglong2 g1 = r0[k + 5];    // +ROW
                ulonglong2 g2 = r0[k + 10];   // +2*ROW
                FMA2(accA[2*k  ], g0.x, WA0);
                FMA2(accA[2*k  ], g1.x, WA1);
                FMA2(accA[2*k  ], g2.x, WA2);
                FMA2(accA[2*k+1], g0.y, WA0);
                FMA2(accA[2*k+1], g1.y, WA1);
                FMA2(accA[2*k+1], g2.y, WA2);
                FMA2(accB[2*k  ], g0.x, WB0);
                FMA2(accB[2*k  ], g1.x, WB1);
                FMA2(accB[2*k  ], g2.x, WB2);
                FMA2(accB[2*k+1], g0.y, WB0);
                FMA2(accB[2*k+1], g1.y, WB1);
                FMA2(accB[2*k+1], g2.y, WB2);
            }
        }

        buf_c = buf_n;
    }

    // ---- epilogue ----
    const int xA = x0 + 2 * tx;
    const int yo = y0 + yy;
    float* obase = out + (size_t)yo * IMGN + xA;
    #pragma unroll
    for (int m = 0; m < 8; m++) {
        float2 vA = *reinterpret_cast<float2*>(&accA[m]);
        float2 vB = *reinterpret_cast<float2*>(&accB[m]);
        *(float2*)(obase + (size_t)(2 * m)     * IMGSQ) = make_float2(vA.x, vB.x);
        *(float2*)(obase + (size_t)(2 * m + 1) * IMGSQ) = make_float2(vA.y, vB.y);
    }
}

extern "C" void kernel_launch(void* const* d_in, const int* in_sizes, int n_in,
                              void* d_out, int out_size)
{
    const float* sino      = (const float*)d_in[0];
    const float* thetas    = (const float*)d_in[1];
    const float* positions = (const float*)d_in[2];
    float* out             = (float*)d_out;

    dim3 grid(IMGN / 16, IMGN / 16);
    radon_bp<<<grid, TPB>>>(sino, thetas, positions, out);
}